// round 3
// baseline (speedup 1.0000x reference)
#include <cuda_runtime.h>

#define Bn 4
#define LQ 256
#define LK 512
#define Hd 256

#define QT 32
#define KT 64
#define PITCH 260   // 256 + 4 pad: row bank offset = 4*l -> conflict-free LDS.128 phases

// Scratch (allocation-free rule: device globals)
__device__ float d_qp[Bn*LQ*Hd];       // 1 MB
__device__ float d_kp[Bn*LK*Hd];       // 2 MB
__device__ float d_scores[Bn*LQ*LK];   // 2 MB

__device__ __forceinline__ float tanh_ap(float x) {
    float y;
    asm("tanh.approx.f32 %0, %1;" : "=f"(y) : "f"(x));
    return y;
}

// ---------------------------------------------------------------------------
// Kernel 1: fused projections  C[m,n] = sum_k A[m,k]*W[n,k] + b[n]
// grid.x: 16 q-row-tiles then 32 k-row-tiles (64 rows each); grid.y: 4 n-tiles
// ---------------------------------------------------------------------------
__global__ __launch_bounds__(256) void proj_kernel(
    const float* __restrict__ query, const float* __restrict__ key,
    const float* __restrict__ Wq, const float* __restrict__ bq,
    const float* __restrict__ Wk, const float* __restrict__ bk)
{
    __shared__ float As[16][64];
    __shared__ float Bs[16][64];

    int br = blockIdx.x;
    const float* A; const float* W; const float* bias; float* C;
    int m0;
    if (br < 16) { A = query; W = Wq; bias = bq; C = d_qp; m0 = br * 64; }
    else         { A = key;   W = Wk; bias = bk; C = d_kp; m0 = (br - 16) * 64; }
    int n0 = blockIdx.y * 64;

    int tid = threadIdx.x;
    int lm = tid >> 2;            // 0..63 row within tile (load phase)
    int lk = (tid & 3) << 2;      // k offset within 16-chunk
    int tx = tid & 15, ty = tid >> 4;

    float acc[4][4] = {};

    for (int k0 = 0; k0 < Hd; k0 += 16) {
        float4 a = *(const float4*)&A[(m0 + lm) * Hd + k0 + lk];
        float4 w = *(const float4*)&W[(n0 + lm) * Hd + k0 + lk];
        __syncthreads();
        As[lk + 0][lm] = a.x; As[lk + 1][lm] = a.y; As[lk + 2][lm] = a.z; As[lk + 3][lm] = a.w;
        Bs[lk + 0][lm] = w.x; Bs[lk + 1][lm] = w.y; Bs[lk + 2][lm] = w.z; Bs[lk + 3][lm] = w.w;
        __syncthreads();
        #pragma unroll
        for (int kk = 0; kk < 16; kk++) {
            float4 av = *(float4*)&As[kk][ty * 4];
            float4 bv = *(float4*)&Bs[kk][tx * 4];
            float am[4] = {av.x, av.y, av.z, av.w};
            float bn[4] = {bv.x, bv.y, bv.z, bv.w};
            #pragma unroll
            for (int i = 0; i < 4; i++)
                #pragma unroll
                for (int j = 0; j < 4; j++)
                    acc[i][j] += am[i] * bn[j];
        }
    }

    float4 bb = *(const float4*)&bias[n0 + tx * 4];
    float bbv[4] = {bb.x, bb.y, bb.z, bb.w};
    #pragma unroll
    for (int i = 0; i < 4; i++) {
        int row = m0 + ty * 4 + i;
        float4 r;
        r.x = acc[i][0] + bbv[0]; r.y = acc[i][1] + bbv[1];
        r.z = acc[i][2] + bbv[2]; r.w = acc[i][3] + bbv[3];
        *(float4*)&C[row * Hd + n0 + tx * 4] = r;
    }
}

// ---------------------------------------------------------------------------
// Kernel 2: scores[b,q,l] = sum_h tanh(qp[b,q,h]+kp[b,l,h]) * v[h] + bv, masked
// grid (LK/KT=8, LQ/QT=8, B=4) = 256 blocks; 256 thr; per-thread 2q x 4l tile
// MUFU-bound by design (~1 tanh.approx per element).
// ---------------------------------------------------------------------------
__global__ __launch_bounds__(256, 2) void scores_kernel(
    const int* __restrict__ mask, const float* __restrict__ v,
    const float* __restrict__ bvp)
{
    extern __shared__ float sm[];
    float* sq = sm;                       // QT * PITCH
    float* sk = sm + QT * PITCH;          // KT * PITCH
    float* sv = sk + KT * PITCH;          // Hd

    int b = blockIdx.z, q0 = blockIdx.y * QT, k0 = blockIdx.x * KT;
    int tid = threadIdx.x;

    const float* qg_ptr = d_qp + ((size_t)(b * LQ + q0)) * Hd;
    #pragma unroll
    for (int i = tid; i < QT * 64; i += 256) {
        int r = i >> 6, c = (i & 63) << 2;
        *(float4*)&sq[r * PITCH + c] = *(const float4*)&qg_ptr[r * Hd + c];
    }
    const float* kg_ptr = d_kp + ((size_t)(b * LK + k0)) * Hd;
    #pragma unroll
    for (int i = tid; i < KT * 64; i += 256) {
        int r = i >> 6, c = (i & 63) << 2;
        *(float4*)&sk[r * PITCH + c] = *(const float4*)&kg_ptr[r * Hd + c];
    }
    if (tid < 64) *(float4*)&sv[tid * 4] = *(const float4*)&v[tid * 4];
    __syncthreads();

    int lg = tid & 15;       // l base: accumulators cover l = lg + 16*j
    int qg = tid >> 4;       // 0..15: rows qg*2, qg*2+1

    const float* qa  = sq + (qg * 2) * PITCH;
    const float* qbp = qa + PITCH;
    const float* kp0 = sk + lg * PITCH;

    float acc[2][4] = {};

    #pragma unroll 4
    for (int h = 0; h < Hd; h += 4) {
        float4 vv = *(const float4*)&sv[h];
        float4 a0 = *(const float4*)&qa[h];
        float4 a1 = *(const float4*)&qbp[h];
        float4 b0 = *(const float4*)&kp0[h];
        float4 b1 = *(const float4*)&kp0[16 * PITCH + h];
        float4 b2 = *(const float4*)&kp0[32 * PITCH + h];
        float4 b3 = *(const float4*)&kp0[48 * PITCH + h];

        float av[2][4] = {{a0.x, a0.y, a0.z, a0.w}, {a1.x, a1.y, a1.z, a1.w}};
        float bw[4][4] = {{b0.x, b0.y, b0.z, b0.w}, {b1.x, b1.y, b1.z, b1.w},
                          {b2.x, b2.y, b2.z, b2.w}, {b3.x, b3.y, b3.z, b3.w}};
        float vw[4] = {vv.x, vv.y, vv.z, vv.w};

        #pragma unroll
        for (int j = 0; j < 4; j++)
            #pragma unroll
            for (int i = 0; i < 2; i++)
                #pragma unroll
                for (int c = 0; c < 4; c++)
                    acc[i][j] += tanh_ap(av[i][c] + bw[j][c]) * vw[c];
    }

    float bvs = bvp[0];
    int mk[4];
    #pragma unroll
    for (int j = 0; j < 4; j++) mk[j] = mask[b * LK + k0 + lg + 16 * j];

    #pragma unroll
    for (int i = 0; i < 2; i++) {
        int q = q0 + qg * 2 + i;
        float* outr = d_scores + ((size_t)(b * LQ + q)) * LK + k0;
        #pragma unroll
        for (int j = 0; j < 4; j++) {
            float sc = acc[i][j] + bvs;
            if (mk[j] == 0) sc = -1e30f;   // exp underflows to exactly 0, matches -inf path
            outr[lg + 16 * j] = sc;
        }
    }
}

// ---------------------------------------------------------------------------
// Kernel 3: per-row softmax over LK=512 (masked scores already in d_scores),
// writes attn_weights, then fused AV GEMM for attn_output.
// grid (LQ/16=16, B=4, hsplit=2) = 128 blocks; 256 thr.
// ---------------------------------------------------------------------------
__global__ __launch_bounds__(256) void softmax_av_kernel(
    const float* __restrict__ value, float* __restrict__ out)
{
    __shared__ float ws[16 * 512];   // row stride 512: softmax strided reads conflict-free

    int b = blockIdx.y, qbase = blockIdx.x * 16, hs = blockIdx.z;
    int tid = threadIdx.x;

    const float* sc = d_scores + ((size_t)(b * LQ + qbase)) * LK;
    for (int i = tid; i < 2048; i += 256)
        ((float4*)ws)[i] = ((const float4*)sc)[i];
    __syncthreads();

    int w = tid >> 5, lane = tid & 31;
    float* outw = out + (size_t)Bn * LQ * Hd;   // weights segment of d_out

    #pragma unroll
    for (int rr = 0; rr < 2; rr++) {
        int r = w * 2 + rr;
        float* row = ws + r * 512;
        float m = -1e30f;
        #pragma unroll
        for (int t = 0; t < 16; t++) m = fmaxf(m, row[lane + 32 * t]);
        #pragma unroll
        for (int off = 16; off; off >>= 1) m = fmaxf(m, __shfl_xor_sync(0xffffffff, m, off));
        float e[16]; float s = 0.f;
        #pragma unroll
        for (int t = 0; t < 16; t++) { e[t] = __expf(row[lane + 32 * t] - m); s += e[t]; }
        #pragma unroll
        for (int off = 16; off; off >>= 1) s += __shfl_xor_sync(0xffffffff, s, off);
        float inv = 1.0f / s;
        float* og = outw + ((size_t)(b * LQ + qbase + r)) * LK;
        #pragma unroll
        for (int t = 0; t < 16; t++) {
            float wv = e[t] * inv;
            row[lane + 32 * t] = wv;
            if (hs == 0) og[lane + 32 * t] = wv;   // write weights once
        }
    }
    __syncthreads();

    // AV GEMM: out[b, qbase+row, h] = sum_l w[row,l] * value[b,l,h]
    int hg = tid & 31, qg = tid >> 5;            // 32 h-groups x 8 q-groups
    int h = hs * 128 + hg * 4;
    const float* vp = value + ((size_t)b * LK) * Hd + h;
    const float* w0 = ws + (qg * 2) * 512;
    const float* w1 = w0 + 512;

    float acc[2][4] = {};
    #pragma unroll 4
    for (int l = 0; l < LK; l++) {
        float4 val = *(const float4*)&vp[(size_t)l * Hd];
        float x0 = w0[l], x1 = w1[l];
        acc[0][0] += x0 * val.x; acc[0][1] += x0 * val.y;
        acc[0][2] += x0 * val.z; acc[0][3] += x0 * val.w;
        acc[1][0] += x1 * val.x; acc[1][1] += x1 * val.y;
        acc[1][2] += x1 * val.z; acc[1][3] += x1 * val.w;
    }
    #pragma unroll
    for (int i = 0; i < 2; i++) {
        int q = qbase + qg * 2 + i;
        float4 r;
        r.x = acc[i][0]; r.y = acc[i][1]; r.z = acc[i][2]; r.w = acc[i][3];
        *(float4*)&out[((size_t)(b * LQ + q)) * Hd + h] = r;
    }
}

// ---------------------------------------------------------------------------
extern "C" void kernel_launch(void* const* d_in, const int* in_sizes, int n_in,
                              void* d_out, int out_size)
{
    const float* query = (const float*)d_in[0];
    const float* key   = (const float*)d_in[1];
    const float* value = (const float*)d_in[2];
    const int*   mask  = (const int*)  d_in[3];
    const float* Wq    = (const float*)d_in[4];
    const float* bq    = (const float*)d_in[5];
    const float* Wk    = (const float*)d_in[6];
    const float* bk    = (const float*)d_in[7];
    const float* v     = (const float*)d_in[8];
    const float* bv    = (const float*)d_in[9];
    float* out = (float*)d_out;

    (void)in_sizes; (void)n_in; (void)out_size;

    proj_kernel<<<dim3(48, 4), 256>>>(query, key, Wq, bq, Wk, bk);

    size_t smem2 = (size_t)(QT * PITCH + KT * PITCH + Hd) * sizeof(float);  // 100864 B
    cudaFuncSetAttribute(scores_kernel, cudaFuncAttributeMaxDynamicSharedMemorySize, (int)smem2);
    scores_kernel<<<dim3(LK / KT, LQ / QT, Bn), 256, smem2>>>(mask, v, bv);

    softmax_av_kernel<<<dim3(LQ / 16, Bn, 2), 256>>>(value, out);
}